// round 4
// baseline (speedup 1.0000x reference)
#include <cuda_runtime.h>
#include <cstdint>

#define BATCH 2048
#define NH    512
#define HC    256
#define TILE  16
#define NKB   (NH / 8)     // 64 k-blocks of 8
#define DEPTH 6            // cp.async pipeline stages (8KB each)
#define IDXCAP 2048

// smem layout in floats
#define S_IN   0
#define S_LOG  (TILE * NH)                 // 8192
#define S_W    (S_LOG + TILE * HC)         // 12288
#define S_IDX  (S_W + DEPTH * 8 * HC)      // 24576
#define S_CNT  (S_IDX + IDXCAP)            // 26624
#define SMEM_FLOATS (S_CNT + 8)
#define SMEM_BYTES  (SMEM_FLOATS * 4)      // 106,528 B -> 2 CTAs/SM

__device__ float g_top_prob[BATCH];
__device__ float g_bot_prob[BATCH];

// ---------------- packed f32x2 + async-copy helpers ----------------
__device__ __forceinline__ uint64_t pack2(float lo, float hi) {
    uint64_t d; asm("mov.b64 %0, {%1,%2};" : "=l"(d) : "f"(lo), "f"(hi)); return d;
}
__device__ __forceinline__ void unpack2(uint64_t v, float& lo, float& hi) {
    asm("mov.b64 {%0,%1}, %2;" : "=f"(lo), "=f"(hi) : "l"(v));
}
__device__ __forceinline__ uint64_t fma2(uint64_t a, uint64_t b, uint64_t c) {
    uint64_t d; asm("fma.rn.f32x2 %0, %1, %2, %3;" : "=l"(d) : "l"(a), "l"(b), "l"(c)); return d;
}
__device__ __forceinline__ void lds_v2u64(uint64_t& a, uint64_t& b, uint32_t addr) {
    asm volatile("ld.shared.v2.u64 {%0,%1}, [%2];" : "=l"(a), "=l"(b) : "r"(addr));
}
__device__ __forceinline__ void cp16(uint32_t dst, const float* src) {
    asm volatile("cp.async.cg.shared.global [%0], [%1], 16;" :: "r"(dst), "l"(src) : "memory");
}
#define CP_COMMIT() asm volatile("cp.async.commit_group;" ::: "memory")
#define CP_WAIT(n)  asm volatile("cp.async.wait_group %0;" :: "n"(n) : "memory")

// issue first DEPTH stages of W (each thread 16B per stage)
__device__ __forceinline__ void w_prologue(float* sm, const float* __restrict__ Wp, int tid) {
    uint32_t sw = (uint32_t)__cvta_generic_to_shared(sm + S_W);
#pragma unroll
    for (int s = 0; s < DEPTH; s++) {
        cp16(sw + (uint32_t)(s * 8 * HC + tid * 4) * 4, Wp + s * 8 * HC + tid * 4);
        CP_COMMIT();
    }
}

// ---------------------------------------------------------------------------
// Pipelined GEMM: SA rows x 256 cols, K=512. W streamed gmem->smem via
// cp.async (DEPTH stages). Thread owns col j = tid&255; half h = tid>>8
// consumes k-blocks with (kb&1)==h. Writes logits (+bias) to s_log.
// Caller must have run w_prologue and synced after loading s_in.
// ---------------------------------------------------------------------------
template <int SA>
__device__ __forceinline__ void gemm_pipe(float* sm, const float* __restrict__ Wp,
                                          int tid, float biasj)
{
    int j = tid & (HC - 1);
    int half = tid >> 8;
    float* s_log = sm + S_LOG;
    const float* s_w = sm + S_W;
    uint32_t sin = (uint32_t)__cvta_generic_to_shared(sm);
    uint32_t sw  = (uint32_t)__cvta_generic_to_shared(sm + S_W);

    uint64_t acc[SA];
#pragma unroll
    for (int s = 0; s < SA; s++) acc[s] = 0ull;

    int st = 0;
#pragma unroll 2
    for (int kb = 0; kb < NKB; kb++) {
        CP_WAIT(DEPTH - 1);          // stage kb's data resident (this thread's piece)
        __syncthreads();             // ... and everyone else's

        if ((kb & 1) == half) {
            const float* wrow = s_w + st * (8 * HC) + j;
            float a0 = wrow[0 * HC], a1 = wrow[1 * HC];
            uint64_t w01 = pack2(a0, a1);
            a0 = wrow[2 * HC]; a1 = wrow[3 * HC];
            uint64_t w23 = pack2(a0, a1);
            a0 = wrow[4 * HC]; a1 = wrow[5 * HC];
            uint64_t w45 = pack2(a0, a1);
            a0 = wrow[6 * HC]; a1 = wrow[7 * HC];
            uint64_t w67 = pack2(a0, a1);

            uint32_t a = sin + (uint32_t)(kb * 8) * 4;
#pragma unroll
            for (int s = 0; s < SA; s++) {
                uint64_t v01, v23, v45, v67;
                lds_v2u64(v01, v23, a);
                lds_v2u64(v45, v67, a + 16);
                acc[s] = fma2(v01, w01, acc[s]);
                acc[s] = fma2(v23, w23, acc[s]);
                acc[s] = fma2(v45, w45, acc[s]);
                acc[s] = fma2(v67, w67, acc[s]);
                a += NH * 4;
            }
        }
        __syncthreads();             // stage st fully consumed -> safe to refill

        int kn = kb + DEPTH;
        if (kn < NKB)
            cp16(sw + (uint32_t)(st * 8 * HC + tid * 4) * 4, Wp + kn * 8 * HC + tid * 4);
        CP_COMMIT();
        if (++st == DEPTH) st = 0;
    }

    float r[SA];
#pragma unroll
    for (int s = 0; s < SA; s++) {
        float lo, hi; unpack2(acc[s], lo, hi);
        r[s] = lo + hi;
    }
    if (half == 1) {
#pragma unroll
        for (int s = 0; s < SA; s++) s_log[s * HC + j] = r[s];
    }
    __syncthreads();
    if (half == 0) {
#pragma unroll
        for (int s = 0; s < SA; s++) s_log[s * HC + j] = r[s] + s_log[s * HC + j] + biasj;
    }
    __syncthreads();
}

__device__ __forceinline__ void softmax_row(const float* row, int lane,
                                            float& m_out, float& sum_out)
{
    float m = -1e30f;
#pragma unroll
    for (int c = lane; c < HC; c += 32) m = fmaxf(m, row[c]);
#pragma unroll
    for (int o = 16; o > 0; o >>= 1) m = fmaxf(m, __shfl_xor_sync(0xffffffffu, m, o));
    float sum = 0.f;
#pragma unroll
    for (int c = lane; c < HC; c += 32) sum += __expf(row[c] - m);
#pragma unroll
    for (int o = 16; o > 0; o >>= 1) sum += __shfl_xor_sync(0xffffffffu, sum, o);
    m_out = m; sum_out = sum;
}

// ---------------------------------------------------------------------------
// Fused kernel: 384 CTAs. bid%3==2 -> top role (128 tiles of 16 samples);
// else -> bottom role (one parent each, self-grouped). Roles interleaved so
// DRAM-bound and fma-bound CTAs share SMs.
// ---------------------------------------------------------------------------
__global__ __launch_bounds__(512, 2) void fused_kernel(
    const float* __restrict__ inputs, const int* __restrict__ labels,
    const int* __restrict__ parent,
    const float* __restrict__ topW, const float* __restrict__ topB,
    const float* __restrict__ botW, const float* __restrict__ botB)
{
    extern __shared__ float sm[];
    int bid = blockIdx.x;
    int tid = threadIdx.x;
    int j = tid & (HC - 1);
    int wid = tid >> 5, lane = tid & 31;

    if (bid % 3 == 2) {
        // ----------------- TOP role -----------------
        int b0 = (bid / 3) * TILE;
        w_prologue(sm, topW, tid);

        const float4* gin = (const float4*)(inputs + (size_t)b0 * NH);
        float4* s4 = (float4*)sm;
#pragma unroll
        for (int i = 0; i < TILE * NH / 4 / 512; i++) s4[tid + i * 512] = gin[tid + i * 512];
        __syncthreads();

        gemm_pipe<TILE>(sm, topW, tid, topB[j]);

        const float* row = sm + S_LOG + wid * HC;
        float m, sum;
        softmax_row(row, lane, m, sum);
        if (lane == 0) {
            int b = b0 + wid;
            int p = parent[b];
            g_top_prob[b] = __expf(row[p] - m) / sum;
        }
    } else {
        // ----------------- BOTTOM role -----------------
        int p = (bid / 3) * 2 + (bid % 3);
        int* s_idx = (int*)(sm + S_IDX);
        int* s_cnt = (int*)(sm + S_CNT);
        if (tid == 0) *s_cnt = 0;
        __syncthreads();
        for (int i = tid; i < BATCH; i += 512) {
            if (parent[i] == p) {
                int q = atomicAdd(s_cnt, 1);
                if (q < IDXCAP) s_idx[q] = i;
            }
        }
        __syncthreads();
        int n = min(*s_cnt, IDXCAP);
        if (n == 0) return;

        const float* Wp = botW + (size_t)p * NH * HC;
        float biasj = botB[(size_t)p * HC + j];

        for (int c0 = 0; c0 < n; c0 += TILE) {
            int S = min(TILE, n - c0);
            __syncthreads();               // prev softmax done with s_log
            w_prologue(sm, Wp, tid);

            for (int i = tid; i < S * (NH / 4); i += 512) {
                int s = i >> 7, q = i & 127;
                int b = s_idx[c0 + s];
                ((float4*)(sm + s * NH))[q] = ((const float4*)(inputs + (size_t)b * NH))[q];
            }
            __syncthreads();

            switch ((S + 3) >> 2) {
                case 1:  gemm_pipe<4>(sm, Wp, tid, biasj);  break;
                case 2:  gemm_pipe<8>(sm, Wp, tid, biasj);  break;
                case 3:  gemm_pipe<12>(sm, Wp, tid, biasj); break;
                default: gemm_pipe<16>(sm, Wp, tid, biasj); break;
            }

            if (wid < S) {
                const float* row = sm + S_LOG + wid * HC;
                float m, sum;
                softmax_row(row, lane, m, sum);
                if (lane == 0) {
                    int b = s_idx[c0 + wid];
                    int l = labels[b];
                    g_bot_prob[b] = __expf(row[l] - m) / sum;
                }
            }
        }
    }
}

// ---------------------------------------------------------------------------
__global__ void finalize_kernel(float* __restrict__ out) {
    int i = blockIdx.x * blockDim.x + threadIdx.x;
    if (i < BATCH) out[i] = g_top_prob[i] * g_bot_prob[i];
}

// ---------------------------------------------------------------------------
extern "C" void kernel_launch(void* const* d_in, const int* in_sizes, int n_in,
                              void* d_out, int out_size) {
    const float* inputs = (const float*)d_in[0];
    const int*   labels = (const int*)d_in[1];
    const int*   parent = (const int*)d_in[2];
    const float* topW   = (const float*)d_in[3];
    const float* topB   = (const float*)d_in[4];
    const float* botW   = (const float*)d_in[5];
    const float* botB   = (const float*)d_in[6];
    float* out = (float*)d_out;

    cudaFuncSetAttribute(fused_kernel,
                         cudaFuncAttributeMaxDynamicSharedMemorySize, SMEM_BYTES);

    fused_kernel<<<384, 512, SMEM_BYTES>>>(inputs, labels, parent,
                                           topW, topB, botW, botB);
    finalize_kernel<<<4, 512>>>(out);
}

// round 5
// speedup vs baseline: 1.2803x; 1.2803x over previous
#include <cuda_runtime.h>
#include <cstdint>

#define BATCH 2048
#define NH    512
#define HC    256
#define TILE  16
#define IDXCAP 128

// dynamic smem layout (floats)
#define S_LOG  (TILE * NH)            // s_in: [0, 8192)
#define S_IDX  (S_LOG + TILE * HC)    // s_log: [8192, 12288)
#define S_CNT  (S_IDX + IDXCAP)
#define SMEM_FLOATS (S_CNT + 4)
#define SMEM_BYTES  (SMEM_FLOATS * 4) // ~49.7 KB -> 2 CTAs/SM

__device__ float g_top_prob[BATCH];
__device__ float g_bot_prob[BATCH];

// ---------------- packed f32x2 helpers ----------------
__device__ __forceinline__ uint64_t pack2(float lo, float hi) {
    uint64_t d; asm("mov.b64 %0, {%1,%2};" : "=l"(d) : "f"(lo), "f"(hi)); return d;
}
__device__ __forceinline__ void unpack2(uint64_t v, float& lo, float& hi) {
    asm("mov.b64 {%0,%1}, %2;" : "=f"(lo), "=f"(hi) : "l"(v));
}
__device__ __forceinline__ uint64_t fma2(uint64_t a, uint64_t b, uint64_t c) {
    uint64_t d; asm("fma.rn.f32x2 %0, %1, %2, %3;" : "=l"(d) : "l"(a), "l"(b), "l"(c)); return d;
}
__device__ __forceinline__ void lds_v2u64(uint64_t& a, uint64_t& b, uint32_t addr) {
    asm volatile("ld.shared.v2.u64 {%0,%1}, [%2];" : "=l"(a), "=l"(b) : "r"(addr));
}

// ---------------------------------------------------------------------------
// R3-proven GEMM body: SA rows x 256 cols, K split in halves of 256 across
// thread halves. Register ping-pong prefetch of W (2 blocks of 8 k deep).
// No barriers in the mainloop. Writes logits (+bias) to s_log.
// ---------------------------------------------------------------------------
template <int SA>
__device__ __forceinline__ void gemm_body(
    const float* s_in_k, float* s_log,
    const float* __restrict__ wc,    // W + j + k0*HC
    int j, int half, float biasj)
{
    uint64_t acc[SA];
#pragma unroll
    for (int s = 0; s < SA; s++) acc[s] = 0ull;

    uint32_t sb = (uint32_t)__cvta_generic_to_shared(s_in_k);

    const int NBLK = (NH / 2) / 8;   // 32 blocks of 8 k
    float A[8], B[8];
#pragma unroll
    for (int i = 0; i < 8; i++) A[i] = wc[(size_t)i * HC];
#pragma unroll
    for (int i = 0; i < 8; i++) B[i] = wc[(size_t)(8 + i) * HC];

    for (int ib = 0; ib < NBLK; ib += 2) {
        {   // block ib (buffer A), prefetch A <- ib+2
            uint64_t wA = pack2(A[0], A[1]), wB = pack2(A[2], A[3]);
            uint64_t wC = pack2(A[4], A[5]), wD = pack2(A[6], A[7]);
            int ip = (ib + 2 < NBLK) ? (ib + 2) : ib;
            const float* wp = wc + (size_t)ip * 8 * HC;
#pragma unroll
            for (int i = 0; i < 8; i++) A[i] = wp[(size_t)i * HC];

            uint32_t a = sb + ib * 32;
#pragma unroll
            for (int s = 0; s < SA; s++) {
                uint64_t v01, v23, v45, v67;
                lds_v2u64(v01, v23, a);
                lds_v2u64(v45, v67, a + 16);
                acc[s] = fma2(v01, wA, acc[s]);
                acc[s] = fma2(v23, wB, acc[s]);
                acc[s] = fma2(v45, wC, acc[s]);
                acc[s] = fma2(v67, wD, acc[s]);
                a += NH * 4;
            }
        }
        {   // block ib+1 (buffer B), prefetch B <- ib+3
            uint64_t wA = pack2(B[0], B[1]), wB = pack2(B[2], B[3]);
            uint64_t wC = pack2(B[4], B[5]), wD = pack2(B[6], B[7]);
            int ip = (ib + 3 < NBLK) ? (ib + 3) : (ib + 1);
            const float* wp = wc + (size_t)ip * 8 * HC;
#pragma unroll
            for (int i = 0; i < 8; i++) B[i] = wp[(size_t)i * HC];

            uint32_t a = sb + (ib + 1) * 32;
#pragma unroll
            for (int s = 0; s < SA; s++) {
                uint64_t v01, v23, v45, v67;
                lds_v2u64(v01, v23, a);
                lds_v2u64(v45, v67, a + 16);
                acc[s] = fma2(v01, wA, acc[s]);
                acc[s] = fma2(v23, wB, acc[s]);
                acc[s] = fma2(v45, wC, acc[s]);
                acc[s] = fma2(v67, wD, acc[s]);
                a += NH * 4;
            }
        }
    }

    float r[SA];
#pragma unroll
    for (int s = 0; s < SA; s++) {
        float lo, hi; unpack2(acc[s], lo, hi);
        r[s] = lo + hi;
    }
    if (half == 1) {
#pragma unroll
        for (int s = 0; s < SA; s++) s_log[s * HC + j] = r[s];
    }
    __syncthreads();
    if (half == 0) {
#pragma unroll
        for (int s = 0; s < SA; s++) s_log[s * HC + j] = r[s] + s_log[s * HC + j] + biasj;
    }
    __syncthreads();
}

__device__ __forceinline__ void softmax_row(const float* row, int lane,
                                            float& m_out, float& sum_out)
{
    float m = -1e30f;
#pragma unroll
    for (int c = lane; c < HC; c += 32) m = fmaxf(m, row[c]);
#pragma unroll
    for (int o = 16; o > 0; o >>= 1) m = fmaxf(m, __shfl_xor_sync(0xffffffffu, m, o));
    float sum = 0.f;
#pragma unroll
    for (int c = lane; c < HC; c += 32) sum += __expf(row[c] - m);
#pragma unroll
    for (int o = 16; o > 0; o >>= 1) sum += __shfl_xor_sync(0xffffffffu, sum, o);
    m_out = m; sum_out = sum;
}

// ---------------------------------------------------------------------------
// Fused kernel, 256 CTAs (one wave at 2 CTAs/SM).
//   even bid -> top role on sample tile bid/2 (128 tiles of 16)
//   odd  bid -> bottom role on parents {2i, 2i+1}, i=(bid-1)/2
// ---------------------------------------------------------------------------
__global__ __launch_bounds__(512, 2) void fused_kernel(
    const float* __restrict__ inputs, const int* __restrict__ labels,
    const int* __restrict__ parent,
    const float* __restrict__ topW, const float* __restrict__ topB,
    const float* __restrict__ botW, const float* __restrict__ botB)
{
    extern __shared__ float sm[];
    float* s_in  = sm;
    float* s_log = sm + S_LOG;
    int bid = blockIdx.x;
    int tid = threadIdx.x;
    int j = tid & (HC - 1);
    int half = tid >> 8;
    int k0 = half * (NH / 2);
    int wid = tid >> 5, lane = tid & 31;

    if ((bid & 1) == 0) {
        // ----------------- TOP role -----------------
        int b0 = (bid >> 1) * TILE;
        const float4* gin = (const float4*)(inputs + (size_t)b0 * NH);
        float4* s4 = (float4*)s_in;
#pragma unroll
        for (int i = 0; i < TILE * NH / 4 / 512; i++) s4[tid + i * 512] = gin[tid + i * 512];
        __syncthreads();

        gemm_body<TILE>(s_in + k0, s_log, topW + j + (size_t)k0 * HC, j, half, topB[j]);

        const float* row = s_log + wid * HC;
        float m, sum;
        softmax_row(row, lane, m, sum);
        if (lane == 0) {
            int b = b0 + wid;
            int p = parent[b];
            g_top_prob[b] = __expf(row[p] - m) / sum;
        }
    } else {
        // ----------------- BOTTOM role: two parents -----------------
        int p0 = ((bid - 1) >> 1) * 2;
        int* s_idx = (int*)(sm + S_IDX);
        int* s_cnt = (int*)(sm + S_CNT);

        for (int p = p0; p < p0 + 2; p++) {
            __syncthreads();               // reuse of s_idx/s_log across parents
            if (tid == 0) *s_cnt = 0;
            __syncthreads();
            for (int i = tid; i < BATCH; i += 512) {
                if (parent[i] == p) {
                    int q = atomicAdd(s_cnt, 1);
                    if (q < IDXCAP) s_idx[q] = i;
                }
            }
            __syncthreads();
            int n = min(*s_cnt, IDXCAP);
            if (n == 0) continue;

            const float* wc = botW + (size_t)p * NH * HC + j + (size_t)k0 * HC;
            float biasj = botB[(size_t)p * HC + j];

            for (int c0 = 0; c0 < n; c0 += TILE) {
                int S = min(TILE, n - c0);
                __syncthreads();           // prev softmax done with s_log/s_in

                for (int i = tid; i < S * (NH / 4); i += 512) {
                    int s = i >> 7, q = i & 127;
                    int b = s_idx[c0 + s];
                    ((float4*)(s_in + s * NH))[q] = ((const float4*)(inputs + (size_t)b * NH))[q];
                }
                __syncthreads();

                switch ((S + 3) >> 2) {
                    case 1:  gemm_body<4>(s_in + k0, s_log, wc, j, half, biasj);  break;
                    case 2:  gemm_body<8>(s_in + k0, s_log, wc, j, half, biasj);  break;
                    case 3:  gemm_body<12>(s_in + k0, s_log, wc, j, half, biasj); break;
                    default: gemm_body<16>(s_in + k0, s_log, wc, j, half, biasj); break;
                }

                if (wid < S) {
                    const float* row = s_log + wid * HC;
                    float m, sum;
                    softmax_row(row, lane, m, sum);
                    if (lane == 0) {
                        int b = s_idx[c0 + wid];
                        int l = labels[b];
                        g_bot_prob[b] = __expf(row[l] - m) / sum;
                    }
                }
            }
        }
    }
}

// ---------------------------------------------------------------------------
__global__ void finalize_kernel(float* __restrict__ out) {
    int i = blockIdx.x * blockDim.x + threadIdx.x;
    if (i < BATCH) out[i] = g_top_prob[i] * g_bot_prob[i];
}

// ---------------------------------------------------------------------------
extern "C" void kernel_launch(void* const* d_in, const int* in_sizes, int n_in,
                              void* d_out, int out_size) {
    const float* inputs = (const float*)d_in[0];
    const int*   labels = (const int*)d_in[1];
    const int*   parent = (const int*)d_in[2];
    const float* topW   = (const float*)d_in[3];
    const float* topB   = (const float*)d_in[4];
    const float* botW   = (const float*)d_in[5];
    const float* botB   = (const float*)d_in[6];
    float* out = (float*)d_out;

    cudaFuncSetAttribute(fused_kernel,
                         cudaFuncAttributeMaxDynamicSharedMemorySize, SMEM_BYTES);

    fused_kernel<<<256, 512, SMEM_BYTES>>>(inputs, labels, parent,
                                           topW, topB, botW, botB);
    finalize_kernel<<<4, 512>>>(out);
}

// round 6
// speedup vs baseline: 1.6379x; 1.2793x over previous
#include <cuda_runtime.h>
#include <cstdint>

#define BATCH 2048
#define NH    512
#define HC    256
#define TILE  16
#define IDXCAP 128

#define NTOP  128
#define NBOT  168
#define GRID  (NTOP + NBOT)   // 296 = 148 SMs * 2 CTAs

// dynamic smem layout (floats)
#define S_LOG  (TILE * NH)            // s_in: [0, 8192)
#define S_IDX  (S_LOG + TILE * HC)    // s_log: [8192, 12288)
#define S_CNT  (S_IDX + IDXCAP)
#define S_POP  (S_CNT + 1)
#define SMEM_FLOATS (S_POP + 3)
#define SMEM_BYTES  (SMEM_FLOATS * 4) // ~49.7 KB -> 2 CTAs/SM

__device__ float g_top_prob[BATCH];
__device__ float g_bot_prob[BATCH];
__device__ int   g_queue;   // parent work queue cursor (self-resetting)
__device__ int   g_done;    // CTA completion counter (self-resetting)

// ---------------- packed f32x2 helpers ----------------
__device__ __forceinline__ uint64_t pack2(float lo, float hi) {
    uint64_t d; asm("mov.b64 %0, {%1,%2};" : "=l"(d) : "f"(lo), "f"(hi)); return d;
}
__device__ __forceinline__ void unpack2(uint64_t v, float& lo, float& hi) {
    asm("mov.b64 {%0,%1}, %2;" : "=f"(lo), "=f"(hi) : "l"(v));
}
__device__ __forceinline__ uint64_t fma2(uint64_t a, uint64_t b, uint64_t c) {
    uint64_t d; asm("fma.rn.f32x2 %0, %1, %2, %3;" : "=l"(d) : "l"(a), "l"(b), "l"(c)); return d;
}
__device__ __forceinline__ void lds_v2u64(uint64_t& a, uint64_t& b, uint32_t addr) {
    asm volatile("ld.shared.v2.u64 {%0,%1}, [%2];" : "=l"(a), "=l"(b) : "r"(addr));
}

// ---------------------------------------------------------------------------
// Proven GEMM body: SA rows x 256 cols, K split in halves of 256 across
// thread halves. Register ping-pong prefetch of W (2 blocks of 8 k deep).
// No barriers in the mainloop. Writes logits (+bias) to s_log.
// ---------------------------------------------------------------------------
template <int SA>
__device__ __forceinline__ void gemm_body(
    const float* s_in_k, float* s_log,
    const float* __restrict__ wc,    // W + j + k0*HC
    int j, int half, float biasj)
{
    uint64_t acc[SA];
#pragma unroll
    for (int s = 0; s < SA; s++) acc[s] = 0ull;

    uint32_t sb = (uint32_t)__cvta_generic_to_shared(s_in_k);

    const int NBLK = (NH / 2) / 8;   // 32 blocks of 8 k
    float A[8], B[8];
#pragma unroll
    for (int i = 0; i < 8; i++) A[i] = wc[(size_t)i * HC];
#pragma unroll
    for (int i = 0; i < 8; i++) B[i] = wc[(size_t)(8 + i) * HC];

    for (int ib = 0; ib < NBLK; ib += 2) {
        {   // block ib (buffer A), prefetch A <- ib+2
            uint64_t wA = pack2(A[0], A[1]), wB = pack2(A[2], A[3]);
            uint64_t wC = pack2(A[4], A[5]), wD = pack2(A[6], A[7]);
            int ip = (ib + 2 < NBLK) ? (ib + 2) : ib;
            const float* wp = wc + (size_t)ip * 8 * HC;
#pragma unroll
            for (int i = 0; i < 8; i++) A[i] = wp[(size_t)i * HC];

            uint32_t a = sb + ib * 32;
#pragma unroll
            for (int s = 0; s < SA; s++) {
                uint64_t v01, v23, v45, v67;
                lds_v2u64(v01, v23, a);
                lds_v2u64(v45, v67, a + 16);
                acc[s] = fma2(v01, wA, acc[s]);
                acc[s] = fma2(v23, wB, acc[s]);
                acc[s] = fma2(v45, wC, acc[s]);
                acc[s] = fma2(v67, wD, acc[s]);
                a += NH * 4;
            }
        }
        {   // block ib+1 (buffer B), prefetch B <- ib+3
            uint64_t wA = pack2(B[0], B[1]), wB = pack2(B[2], B[3]);
            uint64_t wC = pack2(B[4], B[5]), wD = pack2(B[6], B[7]);
            int ip = (ib + 3 < NBLK) ? (ib + 3) : (ib + 1);
            const float* wp = wc + (size_t)ip * 8 * HC;
#pragma unroll
            for (int i = 0; i < 8; i++) B[i] = wp[(size_t)i * HC];

            uint32_t a = sb + (ib + 1) * 32;
#pragma unroll
            for (int s = 0; s < SA; s++) {
                uint64_t v01, v23, v45, v67;
                lds_v2u64(v01, v23, a);
                lds_v2u64(v45, v67, a + 16);
                acc[s] = fma2(v01, wA, acc[s]);
                acc[s] = fma2(v23, wB, acc[s]);
                acc[s] = fma2(v45, wC, acc[s]);
                acc[s] = fma2(v67, wD, acc[s]);
                a += NH * 4;
            }
        }
    }

    float r[SA];
#pragma unroll
    for (int s = 0; s < SA; s++) {
        float lo, hi; unpack2(acc[s], lo, hi);
        r[s] = lo + hi;
    }
    if (half == 1) {
#pragma unroll
        for (int s = 0; s < SA; s++) s_log[s * HC + j] = r[s];
    }
    __syncthreads();
    if (half == 0) {
#pragma unroll
        for (int s = 0; s < SA; s++) s_log[s * HC + j] = r[s] + s_log[s * HC + j] + biasj;
    }
    __syncthreads();
}

__device__ __forceinline__ void softmax_row(const float* row, int lane,
                                            float& m_out, float& sum_out)
{
    float m = -1e30f;
#pragma unroll
    for (int c = lane; c < HC; c += 32) m = fmaxf(m, row[c]);
#pragma unroll
    for (int o = 16; o > 0; o >>= 1) m = fmaxf(m, __shfl_xor_sync(0xffffffffu, m, o));
    float sum = 0.f;
#pragma unroll
    for (int c = lane; c < HC; c += 32) sum += __expf(row[c] - m);
#pragma unroll
    for (int o = 16; o > 0; o >>= 1) sum += __shfl_xor_sync(0xffffffffu, sum, o);
    m_out = m; sum_out = sum;
}

// ---------------------------------------------------------------------------
// Fused single-wave kernel (grid=296):
//   bid <  NTOP : top role on sample tile bid
//   bid >= NTOP : bottom role, pops parents off global queue until empty
// Last CTA to finish multiplies top*bottom into out and resets counters.
// ---------------------------------------------------------------------------
__global__ __launch_bounds__(512, 2) void fused_kernel(
    const float* __restrict__ inputs, const int* __restrict__ labels,
    const int* __restrict__ parent,
    const float* __restrict__ topW, const float* __restrict__ topB,
    const float* __restrict__ botW, const float* __restrict__ botB,
    float* __restrict__ out)
{
    extern __shared__ float sm[];
    float* s_in  = sm;
    float* s_log = sm + S_LOG;
    int* s_idx = (int*)(sm + S_IDX);
    int* s_cnt = (int*)(sm + S_CNT);
    int* s_pop = (int*)(sm + S_POP);

    int bid = blockIdx.x;
    int tid = threadIdx.x;
    int j = tid & (HC - 1);
    int half = tid >> 8;
    int k0 = half * (NH / 2);
    int wid = tid >> 5, lane = tid & 31;

    if (bid < NTOP) {
        // ----------------- TOP role -----------------
        int b0 = bid * TILE;
        const float4* gin = (const float4*)(inputs + (size_t)b0 * NH);
        float4* s4 = (float4*)s_in;
#pragma unroll
        for (int i = 0; i < TILE * NH / 4 / 512; i++) s4[tid + i * 512] = gin[tid + i * 512];
        __syncthreads();

        gemm_body<TILE>(s_in + k0, s_log, topW + j + (size_t)k0 * HC, j, half, topB[j]);

        const float* row = s_log + wid * HC;
        float m, sum;
        softmax_row(row, lane, m, sum);
        if (lane == 0) {
            int b = b0 + wid;
            int p = parent[b];
            g_top_prob[b] = __expf(row[p] - m) / sum;
        }
    } else {
        // ----------------- BOTTOM role: pop parents from queue -----------------
        for (;;) {
            __syncthreads();                 // protect s_pop / s_idx / s_log reuse
            if (tid == 0) *s_pop = atomicAdd(&g_queue, 1);
            __syncthreads();
            int p = *s_pop;
            if (p >= HC) break;

            if (tid == 0) *s_cnt = 0;
            __syncthreads();
            for (int i = tid; i < BATCH; i += 512) {
                if (parent[i] == p) {
                    int q = atomicAdd(s_cnt, 1);
                    if (q < IDXCAP) s_idx[q] = i;
                }
            }
            __syncthreads();
            int n = min(*s_cnt, IDXCAP);
            if (n == 0) continue;

            const float* wc = botW + (size_t)p * NH * HC + j + (size_t)k0 * HC;
            float biasj = botB[(size_t)p * HC + j];

            for (int c0 = 0; c0 < n; c0 += TILE) {
                int S = min(TILE, n - c0);
                __syncthreads();             // prev softmax done with s_log/s_in

                for (int i = tid; i < S * (NH / 4); i += 512) {
                    int s = i >> 7, q = i & 127;
                    int b = s_idx[c0 + s];
                    ((float4*)(s_in + s * NH))[q] = ((const float4*)(inputs + (size_t)b * NH))[q];
                }
                __syncthreads();

                switch ((S + 3) >> 2) {
                    case 1:  gemm_body<4>(s_in + k0, s_log, wc, j, half, biasj);  break;
                    case 2:  gemm_body<8>(s_in + k0, s_log, wc, j, half, biasj);  break;
                    case 3:  gemm_body<12>(s_in + k0, s_log, wc, j, half, biasj); break;
                    default: gemm_body<16>(s_in + k0, s_log, wc, j, half, biasj); break;
                }

                if (wid < S) {
                    const float* row = s_log + wid * HC;
                    float m, sum;
                    softmax_row(row, lane, m, sum);
                    if (lane == 0) {
                        int b = s_idx[c0 + wid];
                        int l = labels[b];
                        g_bot_prob[b] = __expf(row[l] - m) / sum;
                    }
                }
            }
        }
    }

    // ----------------- last-CTA finalize -----------------
    __syncthreads();
    __threadfence();
    if (tid == 0) *s_pop = atomicAdd(&g_done, 1);
    __syncthreads();
    if (*s_pop == GRID - 1) {
        __threadfence();
#pragma unroll
        for (int i = 0; i < BATCH / 512; i++) {
            int b = tid + i * 512;
            out[b] = g_top_prob[b] * g_bot_prob[b];
        }
        __threadfence();
        if (tid == 0) { g_done = 0; g_queue = 0; }
    }
}

// ---------------------------------------------------------------------------
extern "C" void kernel_launch(void* const* d_in, const int* in_sizes, int n_in,
                              void* d_out, int out_size) {
    const float* inputs = (const float*)d_in[0];
    const int*   labels = (const int*)d_in[1];
    const int*   parent = (const int*)d_in[2];
    const float* topW   = (const float*)d_in[3];
    const float* topB   = (const float*)d_in[4];
    const float* botW   = (const float*)d_in[5];
    const float* botB   = (const float*)d_in[6];
    float* out = (float*)d_out;

    cudaFuncSetAttribute(fused_kernel,
                         cudaFuncAttributeMaxDynamicSharedMemorySize, SMEM_BYTES);

    fused_kernel<<<GRID, 512, SMEM_BYTES>>>(inputs, labels, parent,
                                            topW, topB, botW, botB, out);
}

// round 7
// speedup vs baseline: 1.7273x; 1.0545x over previous
#include <cuda_runtime.h>
#include <cstdint>

#define BATCH 2048
#define NH    512
#define HC    256
#define TILE  16
#define TOPT  8            // samples per top tile
#define IDXCAP 128

#define GRID  296          // 148 SMs * 2 CTAs, one wave
#define NQ    (HC + BATCH / TOPT)   // 256 bottom + 256 top = 512 items

// dynamic smem layout (floats)
#define S_LOG  (TILE * NH)            // s_in: [0, 8192)
#define S_IDX  (S_LOG + TILE * HC)    // s_log: [8192, 12288)
#define S_CNT  (S_IDX + IDXCAP)
#define S_POP  (S_CNT + 1)
#define SMEM_FLOATS (S_POP + 3)
#define SMEM_BYTES  (SMEM_FLOATS * 4) // ~49.7 KB -> 2 CTAs/SM

__device__ float g_top_prob[BATCH];
__device__ float g_bot_prob[BATCH];
__device__ int   g_queue;   // work queue cursor (self-resetting)
__device__ int   g_done;    // CTA completion counter (self-resetting)

// ---------------- packed f32x2 helpers ----------------
__device__ __forceinline__ uint64_t pack2(float lo, float hi) {
    uint64_t d; asm("mov.b64 %0, {%1,%2};" : "=l"(d) : "f"(lo), "f"(hi)); return d;
}
__device__ __forceinline__ void unpack2(uint64_t v, float& lo, float& hi) {
    asm("mov.b64 {%0,%1}, %2;" : "=f"(lo), "=f"(hi) : "l"(v));
}
__device__ __forceinline__ uint64_t fma2(uint64_t a, uint64_t b, uint64_t c) {
    uint64_t d; asm("fma.rn.f32x2 %0, %1, %2, %3;" : "=l"(d) : "l"(a), "l"(b), "l"(c)); return d;
}
__device__ __forceinline__ void lds_v2u64(uint64_t& a, uint64_t& b, uint32_t addr) {
    asm volatile("ld.shared.v2.u64 {%0,%1}, [%2];" : "=l"(a), "=l"(b) : "r"(addr));
}

// ---------------------------------------------------------------------------
// Proven GEMM body: SA rows x 256 cols, K split in halves of 256 across
// thread halves. Register ping-pong prefetch of W (2 blocks of 8 k deep).
// No barriers in the mainloop. Writes logits (+bias) to s_log.
// ---------------------------------------------------------------------------
template <int SA>
__device__ __forceinline__ void gemm_body(
    const float* s_in_k, float* s_log,
    const float* __restrict__ wc,    // W + j + k0*HC
    int j, int half, float biasj)
{
    uint64_t acc[SA];
#pragma unroll
    for (int s = 0; s < SA; s++) acc[s] = 0ull;

    uint32_t sb = (uint32_t)__cvta_generic_to_shared(s_in_k);

    const int NBLK = (NH / 2) / 8;   // 32 blocks of 8 k
    float A[8], B[8];
#pragma unroll
    for (int i = 0; i < 8; i++) A[i] = wc[(size_t)i * HC];
#pragma unroll
    for (int i = 0; i < 8; i++) B[i] = wc[(size_t)(8 + i) * HC];

    for (int ib = 0; ib < NBLK; ib += 2) {
        {   // block ib (buffer A), prefetch A <- ib+2
            uint64_t wA = pack2(A[0], A[1]), wB = pack2(A[2], A[3]);
            uint64_t wC = pack2(A[4], A[5]), wD = pack2(A[6], A[7]);
            int ip = (ib + 2 < NBLK) ? (ib + 2) : ib;
            const float* wp = wc + (size_t)ip * 8 * HC;
#pragma unroll
            for (int i = 0; i < 8; i++) A[i] = wp[(size_t)i * HC];

            uint32_t a = sb + ib * 32;
#pragma unroll
            for (int s = 0; s < SA; s++) {
                uint64_t v01, v23, v45, v67;
                lds_v2u64(v01, v23, a);
                lds_v2u64(v45, v67, a + 16);
                acc[s] = fma2(v01, wA, acc[s]);
                acc[s] = fma2(v23, wB, acc[s]);
                acc[s] = fma2(v45, wC, acc[s]);
                acc[s] = fma2(v67, wD, acc[s]);
                a += NH * 4;
            }
        }
        {   // block ib+1 (buffer B), prefetch B <- ib+3
            uint64_t wA = pack2(B[0], B[1]), wB = pack2(B[2], B[3]);
            uint64_t wC = pack2(B[4], B[5]), wD = pack2(B[6], B[7]);
            int ip = (ib + 3 < NBLK) ? (ib + 3) : (ib + 1);
            const float* wp = wc + (size_t)ip * 8 * HC;
#pragma unroll
            for (int i = 0; i < 8; i++) B[i] = wp[(size_t)i * HC];

            uint32_t a = sb + (ib + 1) * 32;
#pragma unroll
            for (int s = 0; s < SA; s++) {
                uint64_t v01, v23, v45, v67;
                lds_v2u64(v01, v23, a);
                lds_v2u64(v45, v67, a + 16);
                acc[s] = fma2(v01, wA, acc[s]);
                acc[s] = fma2(v23, wB, acc[s]);
                acc[s] = fma2(v45, wC, acc[s]);
                acc[s] = fma2(v67, wD, acc[s]);
                a += NH * 4;
            }
        }
    }

    float r[SA];
#pragma unroll
    for (int s = 0; s < SA; s++) {
        float lo, hi; unpack2(acc[s], lo, hi);
        r[s] = lo + hi;
    }
    if (half == 1) {
#pragma unroll
        for (int s = 0; s < SA; s++) s_log[s * HC + j] = r[s];
    }
    __syncthreads();
    if (half == 0) {
#pragma unroll
        for (int s = 0; s < SA; s++) s_log[s * HC + j] = r[s] + s_log[s * HC + j] + biasj;
    }
    __syncthreads();
}

__device__ __forceinline__ void softmax_row(const float* row, int lane,
                                            float& m_out, float& sum_out)
{
    float m = -1e30f;
#pragma unroll
    for (int c = lane; c < HC; c += 32) m = fmaxf(m, row[c]);
#pragma unroll
    for (int o = 16; o > 0; o >>= 1) m = fmaxf(m, __shfl_xor_sync(0xffffffffu, m, o));
    float sum = 0.f;
#pragma unroll
    for (int c = lane; c < HC; c += 32) sum += __expf(row[c] - m);
#pragma unroll
    for (int o = 16; o > 0; o >>= 1) sum += __shfl_xor_sync(0xffffffffu, sum, o);
    m_out = m; sum_out = sum;
}

// ---------------------------------------------------------------------------
// Single-wave persistent kernel. Global queue of 512 uniform items:
//   item <  HC  : bottom parent p = item (512KB DRAM stream, ~1M MAC)
//   item >= HC  : top tile of 8 samples starting at (item-HC)*8 (~1M MAC, L2)
// All 296 CTAs pop until empty; last CTA to finish writes out and resets.
// ---------------------------------------------------------------------------
__global__ __launch_bounds__(512, 2) void fused_kernel(
    const float* __restrict__ inputs, const int* __restrict__ labels,
    const int* __restrict__ parent,
    const float* __restrict__ topW, const float* __restrict__ topB,
    const float* __restrict__ botW, const float* __restrict__ botB,
    float* __restrict__ out)
{
    extern __shared__ float sm[];
    float* s_in  = sm;
    float* s_log = sm + S_LOG;
    int* s_idx = (int*)(sm + S_IDX);
    int* s_cnt = (int*)(sm + S_CNT);
    int* s_pop = (int*)(sm + S_POP);

    int tid = threadIdx.x;
    int j = tid & (HC - 1);
    int half = tid >> 8;
    int k0 = half * (NH / 2);
    int wid = tid >> 5, lane = tid & 31;

    for (;;) {
        __syncthreads();                 // smem reuse across items
        if (tid == 0) *s_pop = atomicAdd(&g_queue, 1);
        __syncthreads();
        int item = *s_pop;
        if (item >= NQ) break;

        if (item >= HC) {
            // ----------------- TOP tile (8 samples) -----------------
            int b0 = (item - HC) * TOPT;
            const float4* gin = (const float4*)(inputs + (size_t)b0 * NH);
            float4* s4 = (float4*)s_in;
#pragma unroll
            for (int i = 0; i < TOPT * NH / 4 / 512; i++)
                s4[tid + i * 512] = gin[tid + i * 512];
            __syncthreads();

            gemm_body<TOPT>(s_in + k0, s_log, topW + j + (size_t)k0 * HC, j, half, topB[j]);

            if (wid < TOPT) {
                const float* row = s_log + wid * HC;
                float m, sum;
                softmax_row(row, lane, m, sum);
                if (lane == 0) {
                    int b = b0 + wid;
                    int p = parent[b];
                    g_top_prob[b] = __expf(row[p] - m) / sum;
                }
            }
        } else {
            // ----------------- BOTTOM parent -----------------
            int p = item;
            if (tid == 0) *s_cnt = 0;
            __syncthreads();
            for (int i = tid; i < BATCH; i += 512) {
                if (parent[i] == p) {
                    int q = atomicAdd(s_cnt, 1);
                    if (q < IDXCAP) s_idx[q] = i;
                }
            }
            __syncthreads();
            int n = min(*s_cnt, IDXCAP);
            if (n == 0) continue;

            const float* wc = botW + (size_t)p * NH * HC + j + (size_t)k0 * HC;
            float biasj = botB[(size_t)p * HC + j];

            for (int c0 = 0; c0 < n; c0 += TILE) {
                int S = min(TILE, n - c0);
                __syncthreads();             // prev softmax done with s_log/s_in

                for (int i = tid; i < S * (NH / 4); i += 512) {
                    int s = i >> 7, q = i & 127;
                    int b = s_idx[c0 + s];
                    ((float4*)(s_in + s * NH))[q] = ((const float4*)(inputs + (size_t)b * NH))[q];
                }
                __syncthreads();

                switch ((S + 3) >> 2) {
                    case 1:  gemm_body<4>(s_in + k0, s_log, wc, j, half, biasj);  break;
                    case 2:  gemm_body<8>(s_in + k0, s_log, wc, j, half, biasj);  break;
                    case 3:  gemm_body<12>(s_in + k0, s_log, wc, j, half, biasj); break;
                    default: gemm_body<16>(s_in + k0, s_log, wc, j, half, biasj); break;
                }

                if (wid < S) {
                    const float* row = s_log + wid * HC;
                    float m, sum;
                    softmax_row(row, lane, m, sum);
                    if (lane == 0) {
                        int b = s_idx[c0 + wid];
                        int l = labels[b];
                        g_bot_prob[b] = __expf(row[l] - m) / sum;
                    }
                }
            }
        }
    }

    // ----------------- last-CTA finalize -----------------
    __syncthreads();
    __threadfence();
    if (tid == 0) *s_pop = atomicAdd(&g_done, 1);
    __syncthreads();
    if (*s_pop == GRID - 1) {
        __threadfence();
#pragma unroll
        for (int i = 0; i < BATCH / 512; i++) {
            int b = tid + i * 512;
            out[b] = g_top_prob[b] * g_bot_prob[b];
        }
        __threadfence();
        if (tid == 0) { g_done = 0; g_queue = 0; }
    }
}

// ---------------------------------------------------------------------------
extern "C" void kernel_launch(void* const* d_in, const int* in_sizes, int n_in,
                              void* d_out, int out_size) {
    const float* inputs = (const float*)d_in[0];
    const int*   labels = (const int*)d_in[1];
    const int*   parent = (const int*)d_in[2];
    const float* topW   = (const float*)d_in[3];
    const float* topB   = (const float*)d_in[4];
    const float* botW   = (const float*)d_in[5];
    const float* botB   = (const float*)d_in[6];
    float* out = (float*)d_out;

    cudaFuncSetAttribute(fused_kernel,
                         cudaFuncAttributeMaxDynamicSharedMemorySize, SMEM_BYTES);

    fused_kernel<<<GRID, 512, SMEM_BYTES>>>(inputs, labels, parent,
                                            topW, topB, botW, botB, out);
}